// round 8
// baseline (speedup 1.0000x reference)
#include <cuda_runtime.h>
#include <cuda_bf16.h>
#include <cstdint>

// ---------------- problem constants ----------------
#define BATCH   64
#define FEAT    128
#define KDIM    2048
#define NDATA   100000
#define NSAMP   16385               // K+1
#define NPAIR   (BATCH * NSAMP)     // 1,048,640
#define NCE_T_INV (1.0f / 0.07f)
#define M_CONST (16384.0f / 100000.0f)
#define EPS_C   1e-7f

#define ESPLIT  32                  // embed k-splits per side (chunk 64)
#define KCH     64                  // embed k-chunk
#define RBLK    128                 // rows per logits tile
#define NTILE   ((NDATA + RBLK - 1) / RBLK)   // 782
#define SA      136                 // smem row stride (bf16 elems)

#define NBB     222                 // blocks per bank
#define NB      (2 * NBB)           // 444 blocks = 148 SMs x occ 3
#define GSTRIDE (NBB * 256)         // 56832
#define GITER   19                  // ceil(NPAIR / GSTRIDE)

#define SMEM_DYN ((128 + 64) * SA * 2)   // 52224 B: Ws+Fs (P0) / Vs (P2)

// ---------------- device scratch (zero-init; reset each call) ----------------
__device__ float          g_partial[2][ESPLIT][FEAT * BATCH];   // [d*64+b]
__device__ uint32_t       g_hb[2][BATCH * FEAT / 2];
__device__ __nv_bfloat16  g_E[2][(size_t)NDATA * BATCH];
__device__ float          g_Zp[2][NBB];
__device__ float          g_Lp[NB];
__device__ int            g_bars[5][8];

// ---------------- helpers ----------------
__device__ __forceinline__ void ldsm_x4(uint32_t* r, uint32_t addr) {
    asm volatile("ldmatrix.sync.aligned.m8n8.x4.shared.b16 {%0,%1,%2,%3}, [%4];"
                 : "=r"(r[0]), "=r"(r[1]), "=r"(r[2]), "=r"(r[3]) : "r"(addr));
}
__device__ __forceinline__ void mma_bf16(float* c, const uint32_t* a, uint32_t b0, uint32_t b1) {
    asm volatile("mma.sync.aligned.m16n8k16.row.col.f32.bf16.bf16.f32 "
                 "{%0,%1,%2,%3}, {%4,%5,%6,%7}, {%8,%9}, {%0,%1,%2,%3};"
                 : "+f"(c[0]), "+f"(c[1]), "+f"(c[2]), "+f"(c[3])
                 : "r"(a[0]), "r"(a[1]), "r"(a[2]), "r"(a[3]), "r"(b0), "r"(b1));
}
__device__ __forceinline__ uint32_t pack_bf2(float x, float y) {
    __nv_bfloat162 h2 = __floats2bfloat162_rn(x, y);
    return *reinterpret_cast<uint32_t*>(&h2);
}
__device__ __forceinline__ float ld_e_cg(const __nv_bfloat16* p) {
    unsigned short v;
    asm volatile("ld.global.cg.u16 %0, [%1];" : "=h"(v) : "l"(p));
    __nv_bfloat16 b;
    *reinterpret_cast<unsigned short*>(&b) = v;
    return __bfloat162float(b);
}
__device__ __forceinline__ int bar_sum(int idx) {
    volatile int* s = g_bars[idx];
    int t = 0;
#pragma unroll
    for (int i = 0; i < 8; i++) t += s[i];
    return t;
}
__device__ __forceinline__ void gbar(int idx, int u) {
    __syncthreads();
    if (threadIdx.x == 0) {
        __threadfence();
        atomicAdd(&g_bars[idx][u & 7], 1);
        while (bar_sum(idx) < NB) __nanosleep(64);
    }
    __syncthreads();
}

// ================= the one kernel (occupancy 3) =================
__global__ __launch_bounds__(256, 3) void k_fused(
    const float* __restrict__ fs, const float* __restrict__ ft,
    const int*   __restrict__ samp,
    const float* __restrict__ ws, const float* __restrict__ bsv,
    const float* __restrict__ wt, const float* __restrict__ btv,
    const float* __restrict__ mem_v1, const float* __restrict__ mem_v2,
    float* __restrict__ out)
{
    extern __shared__ __align__(16) char dsm[];
    __shared__ float  s_red[8];
    __shared__ double s_dd[8];
    __shared__ float  s_z;

    const int u    = blockIdx.x;
    const int tid  = threadIdx.x;
    const int lane = tid & 31, warp = tid >> 5;
    const int lr = lane & 7, q = lane >> 3;

    // ---------------- P0: embed GEMM via MMA, split-K (64 blocks) ----------------
    if (u < 2 * ESPLIT) {
        const int which = u >> 5;
        const int split = u & 31;
        const int k0 = split * KCH;
        const float* W = which ? wt : ws;
        const float* F = which ? ft : fs;

        uint16_t* Ws = reinterpret_cast<uint16_t*>(dsm);          // 128 x SA
        uint16_t* Fs = Ws + 128 * SA;                             // 64 x SA

#pragma unroll
        for (int j = 0; j < 8; j++) {
            const int i = tid + j * 256;
            const int row = i >> 4, c4 = i & 15;
            const float4 v = __ldg(reinterpret_cast<const float4*>(W + row * KDIM + k0) + c4);
            uint2 p;
            p.x = pack_bf2(v.x, v.y);
            p.y = pack_bf2(v.z, v.w);
            *reinterpret_cast<uint2*>(&Ws[row * SA + c4 * 4]) = p;
        }
#pragma unroll
        for (int j = 0; j < 4; j++) {
            const int i = tid + j * 256;
            const int row = i >> 4, c4 = i & 15;
            const float4 v = __ldg(reinterpret_cast<const float4*>(F + row * KDIM + k0) + c4);
            uint2 p;
            p.x = pack_bf2(v.x, v.y);
            p.y = pack_bf2(v.z, v.w);
            *reinterpret_cast<uint2*>(&Fs[row * SA + c4 * 4]) = p;
        }
        __syncthreads();

        const uint32_t a_base = (uint32_t)__cvta_generic_to_shared(Ws);
        const uint32_t b_base = (uint32_t)__cvta_generic_to_shared(Fs);
        const int mg = warp & 3, nh = warp >> 2;     // m128 = 4x32, n64 = 2x32
        const int a_r = lr + ((q & 1) << 3), a_k = (q >> 1) << 3;
        const int b_r = lr + ((q >> 1) << 3), b_k = (q & 1) << 3;

        float acc[2][4][4];
#pragma unroll
        for (int mh = 0; mh < 2; mh++)
#pragma unroll
            for (int nf = 0; nf < 4; nf++)
#pragma unroll
                for (int e = 0; e < 4; e++) acc[mh][nf][e] = 0.f;

#pragma unroll
        for (int ks = 0; ks < 4; ks++) {
            const int kk = ks * 16;
            uint32_t a0[4], a1[4], bb0[4], bb1[4];
            ldsm_x4(a0, a_base + (uint32_t)((mg * 32 + a_r) * SA + kk + a_k) * 2u);
            ldsm_x4(a1, a_base + (uint32_t)((mg * 32 + 16 + a_r) * SA + kk + a_k) * 2u);
            ldsm_x4(bb0, b_base + (uint32_t)((nh * 32 + b_r) * SA + kk + b_k) * 2u);
            ldsm_x4(bb1, b_base + (uint32_t)((nh * 32 + 16 + b_r) * SA + kk + b_k) * 2u);
            mma_bf16(acc[0][0], a0, bb0[0], bb0[1]);
            mma_bf16(acc[0][1], a0, bb0[2], bb0[3]);
            mma_bf16(acc[0][2], a0, bb1[0], bb1[1]);
            mma_bf16(acc[0][3], a0, bb1[2], bb1[3]);
            mma_bf16(acc[1][0], a1, bb0[0], bb0[1]);
            mma_bf16(acc[1][1], a1, bb0[2], bb0[3]);
            mma_bf16(acc[1][2], a1, bb1[0], bb1[1]);
            mma_bf16(acc[1][3], a1, bb1[2], bb1[3]);
        }

        float* outp = g_partial[which][split];
        const int er = lane >> 2, ec = lane & 3;
#pragma unroll
        for (int mh = 0; mh < 2; mh++)
#pragma unroll
            for (int nf = 0; nf < 4; nf++) {
                const int rd = mg * 32 + mh * 16 + er;
                const int cb = nh * 32 + nf * 8 + ec * 2;
                float2 v0 = make_float2(acc[mh][nf][0], acc[mh][nf][1]);
                float2 v1 = make_float2(acc[mh][nf][2], acc[mh][nf][3]);
                *reinterpret_cast<float2*>(&outp[rd * BATCH + cb]) = v0;
                *reinterpret_cast<float2*>(&outp[(rd + 8) * BATCH + cb]) = v1;
            }
    }
    gbar(0, u);

    // ---------------- P1: reduce splits + bias + l2norm + pack bf16 (128 blocks) ----------------
    if (u < 128) {
        const int which = u >> 6;
        const int b     = u & 63;
        const float* bias = which ? btv : bsv;
        float s = 0.f;
        if (tid < 128) {
            const int d = tid;
#pragma unroll 8
            for (int sp = 0; sp < ESPLIT; sp++)
                s += __ldcg(&g_partial[which][sp][d * BATCH + b]);
            s += bias[d];
            float sq = s * s;
#pragma unroll
            for (int o = 16; o; o >>= 1) sq += __shfl_xor_sync(0xffffffffu, sq, o);
            if ((tid & 31) == 0) s_red[tid >> 5] = sq;
        }
        __syncthreads();
        if (tid < 128) {
            const float tot = s_red[0] + s_red[1] + s_red[2] + s_red[3];
            const float v = s * rsqrtf(tot);
            const float vn = __shfl_down_sync(0xffffffffu, v, 1);
            if ((tid & 1) == 0)
                g_hb[which][(b * FEAT + tid) >> 1] = pack_bf2(v, vn);
        }
    }
    gbar(1, u);

    // ---------------- P2: dense logits GEMM + fused exp, 4-stage reg ring ----------------
    const int bank = (u >= NBB) ? 1 : 0;
    const int bx = u - bank * NBB;
    {
        const float* __restrict__ mem = bank ? mem_v1 : mem_v2;
        uint16_t* Vs = reinterpret_cast<uint16_t*>(dsm);          // 64 x SA

        for (int i = tid; i < BATCH * 64; i += 256) {
            const int row = i >> 6, c2 = i & 63;
            *reinterpret_cast<uint32_t*>(&Vs[row * SA + c2 * 2]) = __ldcg(&g_hb[bank][i]);
        }
        __syncthreads();

        const uint32_t v_base = (uint32_t)__cvta_generic_to_shared(Vs);
        const int b_row = lr + ((q >> 1) << 3);
        const int b_kh  = (q & 1) << 3;
        uint32_t* Eb = reinterpret_cast<uint32_t*>(g_E[bank]);

        for (int tile = bx; tile < NTILE; tile += NBB) {
            const int r_base = tile * RBLK;
            const int row0 = r_base + warp * 16 + (lane >> 2);
            const int row1 = row0 + 8;
            const int rc0 = row0 < NDATA ? row0 : NDATA - 1;
            const int rc1 = row1 < NDATA ? row1 : NDATA - 1;
            const float* p0 = mem + (size_t)rc0 * FEAT + (lane & 3) * 2;
            const float* p1 = mem + (size_t)rc1 * FEAT + (lane & 3) * 2;

            float2 buf[4][4];   // 4-stage ring, 16 LDG.64 in flight
#define LOAD4(s, ks) {                                                          \
            buf[s][0] = __ldcs(reinterpret_cast<const float2*>(p0 + (ks) * 16));      \
            buf[s][1] = __ldcs(reinterpret_cast<const float2*>(p1 + (ks) * 16));      \
            buf[s][2] = __ldcs(reinterpret_cast<const float2*>(p0 + (ks) * 16 + 8));  \
            buf[s][3] = __ldcs(reinterpret_cast<const float2*>(p1 + (ks) * 16 + 8)); }

            LOAD4(0, 0); LOAD4(1, 1); LOAD4(2, 2); LOAD4(3, 3);

            float acc[8][4];
#pragma unroll
            for (int f = 0; f < 8; f++)
#pragma unroll
                for (int e = 0; e < 4; e++) acc[f][e] = 0.f;

#pragma unroll
            for (int ks = 0; ks < 8; ks++) {
                const int s = ks & 3;
                uint32_t a[4];
#pragma unroll
                for (int e = 0; e < 4; e++) a[e] = pack_bf2(buf[s][e].x, buf[s][e].y);
                if (ks < 4) LOAD4(s, ks + 4);
                const int k0 = ks * 16;
#pragma unroll
                for (int nt = 0; nt < 4; nt++) {
                    uint32_t bb[4];
                    ldsm_x4(bb, v_base + (uint32_t)((nt * 16 + b_row) * SA + k0 + b_kh) * 2u);
                    mma_bf16(acc[nt * 2 + 0], a, bb[0], bb[1]);
                    mma_bf16(acc[nt * 2 + 1], a, bb[2], bb[3]);
                }
            }
#undef LOAD4

            const int cbase = (lane & 3) * 2;
#pragma unroll
            for (int f = 0; f < 8; f++) {
                const int c = (f >> 1) * 16 + (f & 1) * 8 + cbase;
                if (row0 < NDATA)
                    Eb[(size_t)row0 * (BATCH / 2) + (c >> 1)] =
                        pack_bf2(__expf(acc[f][0] * NCE_T_INV), __expf(acc[f][1] * NCE_T_INV));
                if (row1 < NDATA)
                    Eb[(size_t)row1 * (BATCH / 2) + (c >> 1)] =
                        pack_bf2(__expf(acc[f][2] * NCE_T_INV), __expf(acc[f][3] * NCE_T_INV));
            }
        }
    }
    gbar(2, u);

    // ---------------- P3: gather into registers + per-block Z slot ----------------
    const int pbase = bx * 256 + tid;
    float gv[GITER];
    {
#pragma unroll
        for (int i = 0; i < GITER; i++) {
            const int p = pbase + i * GSTRIDE;
            gv[i] = 0.f;
            if (p < NPAIR) {
                const int s = __ldg(&samp[p]);
                const int b = p / NSAMP;
                gv[i] = ld_e_cg(&g_E[bank][(size_t)s * BATCH + b]);
            }
        }
        float lsum = 0.f;
#pragma unroll
        for (int i = 0; i < GITER; i++) lsum += gv[i];
#pragma unroll
        for (int o = 16; o; o >>= 1) lsum += __shfl_xor_sync(0xffffffffu, lsum, o);
        if ((tid & 31) == 0) s_red[tid >> 5] = lsum;
        __syncthreads();
        if (tid == 0) {
            double tot = 0.0;
#pragma unroll
            for (int i = 0; i < 8; i++) tot += (double)s_red[i];
            g_Zp[bank][bx] = (float)tot;
        }
    }
    gbar(3, u);

    // each block reduces its bank's 222 Z slots (deterministic order)
    {
        float zv = (tid < NBB) ? *(volatile float*)&g_Zp[bank][tid] : 0.f;
#pragma unroll
        for (int o = 16; o; o >>= 1) zv += __shfl_xor_sync(0xffffffffu, zv, o);
        if (lane == 0) s_red[warp] = zv;
        __syncthreads();
        if (tid == 0) {
            float zt = 0.f;
#pragma unroll
            for (int i = 0; i < 8; i++) zt += s_red[i];
            s_z = (float)((double)zt * ((double)NDATA / (double)NPAIR));
        }
        __syncthreads();
    }

    // ---------------- P4: loss from registers (batched logs: 10 + 9) ----------------
    {
        const float zinv = 1.0f / s_z;
        float lsum = 0.f;
        float pn = 1.f, pd = 1.f;
#pragma unroll
        for (int i = 0; i < GITER; i++) {
            const int p = pbase + i * GSTRIDE;
            if (p < NPAIR) {
                const float x = gv[i] * zinv;
                const int b = p / NSAMP;
                const bool pos = (p - b * NSAMP) == 0;
                pn *= pos ? x : M_CONST;
                pd *= x + M_CONST + EPS_C;
            }
            if (i == 9 || i == GITER - 1) {
                lsum += __logf(pn / pd);
                pn = 1.f; pd = 1.f;
            }
        }
#pragma unroll
        for (int o = 16; o; o >>= 1) lsum += __shfl_xor_sync(0xffffffffu, lsum, o);
        __syncthreads();
        if ((tid & 31) == 0) s_red[tid >> 5] = lsum;
        __syncthreads();
        if (tid == 0) {
            double tot = 0.0;
#pragma unroll
            for (int i = 0; i < 8; i++) tot += (double)s_red[i];
            g_Lp[u] = (float)tot;
            __threadfence();
            atomicAdd(&g_bars[4][u & 7], 1);
        }
    }

    // ---------------- block 0: finalize + reset ----------------
    if (u == 0) {
        if (tid == 0) {
            while (bar_sum(4) < NB) __nanosleep(64);
        }
        __syncthreads();
        double s = 0.0;
        if (tid < NB) s = (double)*(volatile float*)&g_Lp[tid];
        if (tid + 256 < NB) s += (double)*(volatile float*)&g_Lp[tid + 256];
#pragma unroll
        for (int o = 16; o; o >>= 1) s += __shfl_down_sync(0xffffffffu, s, o);
        if (lane == 0) s_dd[warp] = s;
        __syncthreads();
        if (tid == 0) {
            double t = 0.0;
#pragma unroll
            for (int i = 0; i < 8; i++) t += s_dd[i];
            out[0] = (float)(-t / (double)BATCH);
        }
        if (tid < 40) g_bars[tid >> 3][tid & 7] = 0;
        __threadfence();
    }
}

// ---------------- launcher ----------------
extern "C" void kernel_launch(void* const* d_in, const int* in_sizes, int n_in,
                              void* d_out, int out_size) {
    const float* feat_s     = (const float*)d_in[0];
    const float* feat_t     = (const float*)d_in[1];
    // d_in[2] = idx (unused; positives already in sample_idx[:,0])
    const int*   sample_idx = (const int*)d_in[3];
    const float* w_s        = (const float*)d_in[4];
    const float* b_s        = (const float*)d_in[5];
    const float* w_t        = (const float*)d_in[6];
    const float* b_t        = (const float*)d_in[7];
    const float* mem_v1     = (const float*)d_in[8];
    const float* mem_v2     = (const float*)d_in[9];
    float* out = (float*)d_out;

    cudaFuncSetAttribute(k_fused, cudaFuncAttributeMaxDynamicSharedMemorySize, SMEM_DYN);
    k_fused<<<NB, 256, SMEM_DYN>>>(feat_s, feat_t, sample_idx,
                                   w_s, b_s, w_t, b_t, mem_v1, mem_v2, out);
}

// round 9
// speedup vs baseline: 1.0227x; 1.0227x over previous
#include <cuda_runtime.h>
#include <cuda_bf16.h>
#include <cstdint>

// ---------------- problem constants ----------------
#define BATCH   64
#define FEAT    128
#define KDIM    2048
#define NDATA   100000
#define NSAMP   16385               // K+1
#define NPAIR   (BATCH * NSAMP)     // 1,048,640
#define NCE_T_INV (1.0f / 0.07f)
#define M_CONST (16384.0f / 100000.0f)
#define EPS_C   1e-7f

#define ESPLIT  32                  // embed k-splits per side (chunk 64)
#define KCH     64
#define RBLK    64                  // rows per logits tile (TMA stage)
#define NTILE   ((NDATA + RBLK - 1) / RBLK)   // 1563
#define SA      136                 // smem row stride (bf16 elems)

#define NBB     148                 // blocks per bank
#define NB      (2 * NBB)           // 296 blocks = 148 SMs x occ 2
#define GSTRIDE (NBB * 256)         // 37888
#define GITER   28                  // ceil(NPAIR / GSTRIDE)

// dynamic smem layout (bytes)
#define STAGE_BYTES 32768                    // 64 rows x 512 B fp32
#define ABUF_OFF    (2 * STAGE_BYTES)        // 65536: bf16 A tile 64 x SA
#define VS_OFF      (ABUF_OFF + RBLK * SA * 2)   // 82944
#define MBAR_OFF    (VS_OFF + BATCH * SA * 2)    // 100352
#define SMEM_DYN    (MBAR_OFF + 128)             // 100480

// ---------------- device scratch (zero-init; reset each call) ----------------
__device__ float          g_partial[2][ESPLIT][FEAT * BATCH];
__device__ uint32_t       g_hb[2][BATCH * FEAT / 2];
__device__ __nv_bfloat16  g_E[2][(size_t)NDATA * BATCH];
__device__ float          g_Zp[2][NBB];
__device__ float          g_Lp[NB];
__device__ int            g_bars[5][8];

// ---------------- helpers ----------------
__device__ __forceinline__ void ldsm_x4(uint32_t* r, uint32_t addr) {
    asm volatile("ldmatrix.sync.aligned.m8n8.x4.shared.b16 {%0,%1,%2,%3}, [%4];"
                 : "=r"(r[0]), "=r"(r[1]), "=r"(r[2]), "=r"(r[3]) : "r"(addr));
}
__device__ __forceinline__ void mma_bf16(float* c, const uint32_t* a, uint32_t b0, uint32_t b1) {
    asm volatile("mma.sync.aligned.m16n8k16.row.col.f32.bf16.bf16.f32 "
                 "{%0,%1,%2,%3}, {%4,%5,%6,%7}, {%8,%9}, {%0,%1,%2,%3};"
                 : "+f"(c[0]), "+f"(c[1]), "+f"(c[2]), "+f"(c[3])
                 : "r"(a[0]), "r"(a[1]), "r"(a[2]), "r"(a[3]), "r"(b0), "r"(b1));
}
__device__ __forceinline__ uint32_t pack_bf2(float x, float y) {
    __nv_bfloat162 h2 = __floats2bfloat162_rn(x, y);
    return *reinterpret_cast<uint32_t*>(&h2);
}
__device__ __forceinline__ float ld_e_cg(const __nv_bfloat16* p) {
    unsigned short v;
    asm volatile("ld.global.cg.u16 %0, [%1];" : "=h"(v) : "l"(p));
    __nv_bfloat16 b;
    *reinterpret_cast<unsigned short*>(&b) = v;
    return __bfloat162float(b);
}
// 1-D bulk async copy global -> shared with mbarrier completion (no tensormap)
__device__ __forceinline__ void tma_bulk_1d(uint32_t dst_smem, const void* src,
                                            uint32_t bytes, uint32_t mbar) {
    asm volatile("cp.async.bulk.shared::cta.global.mbarrier::complete_tx::bytes "
                 "[%0], [%1], %2, [%3];"
                 :: "r"(dst_smem), "l"(src), "r"(bytes), "r"(mbar) : "memory");
}
#define MBAR_INIT(a, c) \
    asm volatile("mbarrier.init.shared.b64 [%0], %1;" :: "r"(a), "r"(c) : "memory")
#define MBAR_EXPECT_TX(a, b) \
    asm volatile("mbarrier.arrive.expect_tx.shared.b64 _, [%0], %1;" :: "r"(a), "r"(b) : "memory")
__device__ __forceinline__ void mbar_wait(uint32_t mbar, uint32_t parity) {
    uint32_t done;
    asm volatile(
        "{\n\t.reg .pred p;\n\t"
        "mbarrier.try_wait.parity.acquire.cta.shared::cta.b64 p, [%1], %2;\n\t"
        "selp.b32 %0, 1, 0, p;\n\t}"
        : "=r"(done) : "r"(mbar), "r"(parity) : "memory");
    if (!done) {
        asm volatile(
            "{\n\t.reg .pred P1;\n\t"
            "WL_%=:\n\t"
            "mbarrier.try_wait.parity.acquire.cta.shared::cta.b64 P1, [%0], %1, 0x989680;\n\t"
            "@P1 bra.uni WD_%=;\n\t"
            "bra.uni WL_%=;\n\t"
            "WD_%=:\n\t}"
            :: "r"(mbar), "r"(parity) : "memory");
    }
}
__device__ __forceinline__ int bar_sum(int idx) {
    volatile int* s = g_bars[idx];
    int t = 0;
#pragma unroll
    for (int i = 0; i < 8; i++) t += s[i];
    return t;
}
__device__ __forceinline__ void gbar(int idx, int u) {
    __syncthreads();
    if (threadIdx.x == 0) {
        __threadfence();
        atomicAdd(&g_bars[idx][u & 7], 1);
        while (bar_sum(idx) < NB) __nanosleep(64);
    }
    __syncthreads();
}

// ================= the one kernel (occ 2) =================
__global__ __launch_bounds__(256, 2) void k_fused(
    const float* __restrict__ fs, const float* __restrict__ ft,
    const int*   __restrict__ samp,
    const float* __restrict__ ws, const float* __restrict__ bsv,
    const float* __restrict__ wt, const float* __restrict__ btv,
    const float* __restrict__ mem_v1, const float* __restrict__ mem_v2,
    float* __restrict__ out)
{
    extern __shared__ __align__(16) char dsm[];
    __shared__ float  s_red[8];
    __shared__ double s_dd[8];
    __shared__ float  s_z;

    const int u    = blockIdx.x;
    const int tid  = threadIdx.x;
    const int lane = tid & 31, warp = tid >> 5;
    const int lr = lane & 7, q = lane >> 3;

    // ---------------- P0: embed GEMM via MMA, split-K (64 blocks) ----------------
    if (u < 2 * ESPLIT) {
        const int which = u >> 5;
        const int split = u & 31;
        const int k0 = split * KCH;
        const float* W = which ? wt : ws;
        const float* F = which ? ft : fs;

        uint16_t* Ws = reinterpret_cast<uint16_t*>(dsm);          // 128 x SA
        uint16_t* Fs = Ws + 128 * SA;                             // 64 x SA

#pragma unroll
        for (int j = 0; j < 8; j++) {
            const int i = tid + j * 256;
            const int row = i >> 4, c4 = i & 15;
            const float4 v = __ldg(reinterpret_cast<const float4*>(W + row * KDIM + k0) + c4);
            uint2 p;
            p.x = pack_bf2(v.x, v.y);
            p.y = pack_bf2(v.z, v.w);
            *reinterpret_cast<uint2*>(&Ws[row * SA + c4 * 4]) = p;
        }
#pragma unroll
        for (int j = 0; j < 4; j++) {
            const int i = tid + j * 256;
            const int row = i >> 4, c4 = i & 15;
            const float4 v = __ldg(reinterpret_cast<const float4*>(F + row * KDIM + k0) + c4);
            uint2 p;
            p.x = pack_bf2(v.x, v.y);
            p.y = pack_bf2(v.z, v.w);
            *reinterpret_cast<uint2*>(&Fs[row * SA + c4 * 4]) = p;
        }
        __syncthreads();

        const uint32_t a_base = (uint32_t)__cvta_generic_to_shared(Ws);
        const uint32_t b_base = (uint32_t)__cvta_generic_to_shared(Fs);
        const int mg = warp & 3, nh = warp >> 2;
        const int a_r = lr + ((q & 1) << 3), a_k = (q >> 1) << 3;
        const int b_r = lr + ((q >> 1) << 3), b_k = (q & 1) << 3;

        float acc[2][4][4];
#pragma unroll
        for (int mh = 0; mh < 2; mh++)
#pragma unroll
            for (int nf = 0; nf < 4; nf++)
#pragma unroll
                for (int e = 0; e < 4; e++) acc[mh][nf][e] = 0.f;

#pragma unroll
        for (int ks = 0; ks < 4; ks++) {
            const int kk = ks * 16;
            uint32_t a0[4], a1[4], bb0[4], bb1[4];
            ldsm_x4(a0, a_base + (uint32_t)((mg * 32 + a_r) * SA + kk + a_k) * 2u);
            ldsm_x4(a1, a_base + (uint32_t)((mg * 32 + 16 + a_r) * SA + kk + a_k) * 2u);
            ldsm_x4(bb0, b_base + (uint32_t)((nh * 32 + b_r) * SA + kk + b_k) * 2u);
            ldsm_x4(bb1, b_base + (uint32_t)((nh * 32 + 16 + b_r) * SA + kk + b_k) * 2u);
            mma_bf16(acc[0][0], a0, bb0[0], bb0[1]);
            mma_bf16(acc[0][1], a0, bb0[2], bb0[3]);
            mma_bf16(acc[0][2], a0, bb1[0], bb1[1]);
            mma_bf16(acc[0][3], a0, bb1[2], bb1[3]);
            mma_bf16(acc[1][0], a1, bb0[0], bb0[1]);
            mma_bf16(acc[1][1], a1, bb0[2], bb0[3]);
            mma_bf16(acc[1][2], a1, bb1[0], bb1[1]);
            mma_bf16(acc[1][3], a1, bb1[2], bb1[3]);
        }

        float* outp = g_partial[which][split];
        const int er = lane >> 2, ec = lane & 3;
#pragma unroll
        for (int mh = 0; mh < 2; mh++)
#pragma unroll
            for (int nf = 0; nf < 4; nf++) {
                const int rd = mg * 32 + mh * 16 + er;
                const int cb = nh * 32 + nf * 8 + ec * 2;
                float2 v0 = make_float2(acc[mh][nf][0], acc[mh][nf][1]);
                float2 v1 = make_float2(acc[mh][nf][2], acc[mh][nf][3]);
                *reinterpret_cast<float2*>(&outp[rd * BATCH + cb]) = v0;
                *reinterpret_cast<float2*>(&outp[(rd + 8) * BATCH + cb]) = v1;
            }
    }
    gbar(0, u);

    // ---------------- P1: reduce splits + bias + l2norm + pack bf16 ----------------
    if (u < 128) {
        const int which = u >> 6;
        const int b     = u & 63;
        const float* bias = which ? btv : bsv;
        float s = 0.f;
        if (tid < 128) {
            const int d = tid;
#pragma unroll 8
            for (int sp = 0; sp < ESPLIT; sp++)
                s += __ldcg(&g_partial[which][sp][d * BATCH + b]);
            s += bias[d];
            float sq = s * s;
#pragma unroll
            for (int o = 16; o; o >>= 1) sq += __shfl_xor_sync(0xffffffffu, sq, o);
            if ((tid & 31) == 0) s_red[tid >> 5] = sq;
        }
        __syncthreads();
        if (tid < 128) {
            const float tot = s_red[0] + s_red[1] + s_red[2] + s_red[3];
            const float v = s * rsqrtf(tot);
            const float vn = __shfl_down_sync(0xffffffffu, v, 1);
            if ((tid & 1) == 0)
                g_hb[which][(b * FEAT + tid) >> 1] = pack_bf2(v, vn);
        }
    }
    gbar(1, u);

    // ---------------- P2: TMA-fed bf16 GEMM + fused exp ----------------
    const int bank = (u >= NBB) ? 1 : 0;
    const int bx = u - bank * NBB;
    {
        const float* __restrict__ mem = bank ? mem_v1 : mem_v2;
        uint16_t* Ab = reinterpret_cast<uint16_t*>(dsm + ABUF_OFF);   // 64 x SA bf16
        uint16_t* Vs = reinterpret_cast<uint16_t*>(dsm + VS_OFF);     // 64 x SA bf16
        const uint32_t smem_base = (uint32_t)__cvta_generic_to_shared(dsm);
        const uint32_t mbar0 = smem_base + MBAR_OFF;

        // stage V
        for (int i = tid; i < BATCH * 64; i += 256) {
            const int row = i >> 6, c2 = i & 63;
            *reinterpret_cast<uint32_t*>(&Vs[row * SA + c2 * 2]) = __ldcg(&g_hb[bank][i]);
        }
        // init mbarriers
        if (tid == 0) {
            MBAR_INIT(mbar0, 1);
            MBAR_INIT(mbar0 + 8, 1);
            asm volatile("fence.proxy.async.shared::cta;" ::: "memory");
        }
        __syncthreads();

        const int itcnt = (NTILE - 1 - bx) / NBB + 1;   // 10 or 11

        // prologue: issue tiles 0,1
        if (tid == 0) {
#pragma unroll
            for (int i = 0; i < 2; i++) {
                if (i < itcnt) {
                    const int r0 = (bx + i * NBB) * RBLK;
                    const int rows = (NDATA - r0) < RBLK ? (NDATA - r0) : RBLK;
                    const uint32_t bytes = (uint32_t)rows * (FEAT * 4);
                    MBAR_EXPECT_TX(mbar0 + i * 8, bytes);
                    tma_bulk_1d(smem_base + i * STAGE_BYTES,
                                mem + (size_t)r0 * FEAT, bytes, mbar0 + i * 8);
                }
            }
        }

        const uint32_t ab_base = (uint32_t)__cvta_generic_to_shared(Ab);
        const uint32_t v_base  = (uint32_t)__cvta_generic_to_shared(Vs);
        const int wm = warp & 3, wn = warp >> 2;        // m: 4 x 16 rows, n: 2 x 32 cols
        const int a_r = lr + ((q & 1) << 3), a_k = (q >> 1) << 3;
        const int b_r = lr + ((q >> 1) << 3), b_k = (q & 1) << 3;
        uint32_t* Eb = reinterpret_cast<uint32_t*>(g_E[bank]);

        for (int i = 0; i < itcnt; i++) {
            const int s = i & 1;
            const int ph = (i >> 1) & 1;
            const int tile = bx + i * NBB;
            const int r_base = tile * RBLK;

            if (tid == 0) mbar_wait(mbar0 + s * 8, ph);
            __syncthreads();

            // convert fp32 stage -> bf16 Ab (warp w handles rows w, w+8, ..)
            const float* stg = reinterpret_cast<const float*>(dsm + s * STAGE_BYTES);
#pragma unroll
            for (int j = 0; j < 8; j++) {
                const int row = warp + 8 * j;
                const float4 v = reinterpret_cast<const float4*>(stg + row * FEAT)[lane];
                uint2 p;
                p.x = pack_bf2(v.x, v.y);
                p.y = pack_bf2(v.z, v.w);
                *reinterpret_cast<uint2*>(&Ab[row * SA + lane * 4]) = p;
            }
            __syncthreads();   // stage s free; Ab ready

            // refill stage s with tile i+2
            if (tid == 0 && (i + 2) < itcnt) {
                const int r2 = (bx + (i + 2) * NBB) * RBLK;
                const int rows = (NDATA - r2) < RBLK ? (NDATA - r2) : RBLK;
                const uint32_t bytes = (uint32_t)rows * (FEAT * 4);
                MBAR_EXPECT_TX(mbar0 + s * 8, bytes);
                tma_bulk_1d(smem_base + s * STAGE_BYTES,
                            mem + (size_t)r2 * FEAT, bytes, mbar0 + s * 8);
            }

            // MMA: warp = m16 x n32
            float acc[4][4];
#pragma unroll
            for (int nf = 0; nf < 4; nf++)
#pragma unroll
                for (int e = 0; e < 4; e++) acc[nf][e] = 0.f;

#pragma unroll
            for (int ks = 0; ks < 8; ks++) {
                const int k0 = ks * 16;
                uint32_t a[4], bb0[4], bb1[4];
                ldsm_x4(a, ab_base + (uint32_t)((wm * 16 + a_r) * SA + k0 + a_k) * 2u);
                ldsm_x4(bb0, v_base + (uint32_t)((wn * 32 + b_r) * SA + k0 + b_k) * 2u);
                ldsm_x4(bb1, v_base + (uint32_t)((wn * 32 + 16 + b_r) * SA + k0 + b_k) * 2u);
                mma_bf16(acc[0], a, bb0[0], bb0[1]);
                mma_bf16(acc[1], a, bb0[2], bb0[3]);
                mma_bf16(acc[2], a, bb1[0], bb1[1]);
                mma_bf16(acc[3], a, bb1[2], bb1[3]);
            }

            // epilogue: exp -> bf16 E[r][b]
            const int row0 = r_base + wm * 16 + (lane >> 2);
            const int cbase = wn * 32 + (lane & 3) * 2;
#pragma unroll
            for (int nf = 0; nf < 4; nf++) {
                const int c = cbase + nf * 8;
                if (row0 < NDATA)
                    Eb[(size_t)row0 * (BATCH / 2) + (c >> 1)] =
                        pack_bf2(__expf(acc[nf][0] * NCE_T_INV), __expf(acc[nf][1] * NCE_T_INV));
                if (row0 + 8 < NDATA)
                    Eb[(size_t)(row0 + 8) * (BATCH / 2) + (c >> 1)] =
                        pack_bf2(__expf(acc[nf][2] * NCE_T_INV), __expf(acc[nf][3] * NCE_T_INV));
            }
            __syncthreads();   // Ab free for next convert
        }
    }
    gbar(2, u);

    // ---------------- P3: gather into registers + per-block Z slot ----------------
    const int pbase = bx * 256 + tid;
    float gv[GITER];
    {
#pragma unroll
        for (int i = 0; i < GITER; i++) {
            const int p = pbase + i * GSTRIDE;
            gv[i] = 0.f;
            if (p < NPAIR) {
                const int s = __ldg(&samp[p]);
                const int b = p / NSAMP;
                gv[i] = ld_e_cg(&g_E[bank][(size_t)s * BATCH + b]);
            }
        }
        float lsum = 0.f;
#pragma unroll
        for (int i = 0; i < GITER; i++) lsum += gv[i];
#pragma unroll
        for (int o = 16; o; o >>= 1) lsum += __shfl_xor_sync(0xffffffffu, lsum, o);
        if ((tid & 31) == 0) s_red[tid >> 5] = lsum;
        __syncthreads();
        if (tid == 0) {
            double tot = 0.0;
#pragma unroll
            for (int i = 0; i < 8; i++) tot += (double)s_red[i];
            g_Zp[bank][bx] = (float)tot;
        }
    }
    gbar(3, u);

    // each block reduces its bank's Z slots
    {
        float zv = (tid < NBB) ? *(volatile float*)&g_Zp[bank][tid] : 0.f;
#pragma unroll
        for (int o = 16; o; o >>= 1) zv += __shfl_xor_sync(0xffffffffu, zv, o);
        if (lane == 0) s_red[warp] = zv;
        __syncthreads();
        if (tid == 0) {
            float zt = 0.f;
#pragma unroll
            for (int i = 0; i < 8; i++) zt += s_red[i];
            s_z = (float)((double)zt * ((double)NDATA / (double)NPAIR));
        }
        __syncthreads();
    }

    // ---------------- P4: loss from registers (batched logs) ----------------
    {
        const float zinv = 1.0f / s_z;
        float lsum = 0.f;
        float pn = 1.f, pd = 1.f;
#pragma unroll
        for (int i = 0; i < GITER; i++) {
            const int p = pbase + i * GSTRIDE;
            if (p < NPAIR) {
                const float x = gv[i] * zinv;
                const int b = p / NSAMP;
                const bool pos = (p - b * NSAMP) == 0;
                pn *= pos ? x : M_CONST;
                pd *= x + M_CONST + EPS_C;
            }
            if (i == 13 || i == GITER - 1) {
                lsum += __logf(pn / pd);
                pn = 1.f; pd = 1.f;
            }
        }
#pragma unroll
        for (int o = 16; o; o >>= 1) lsum += __shfl_xor_sync(0xffffffffu, lsum, o);
        __syncthreads();
        if ((tid & 31) == 0) s_red[tid >> 5] = lsum;
        __syncthreads();
        if (tid == 0) {
            double tot = 0.0;
#pragma unroll
            for (int i = 0; i < 8; i++) tot += (double)s_red[i];
            g_Lp[u] = (float)tot;
            __threadfence();
            atomicAdd(&g_bars[4][u & 7], 1);
        }
    }

    // ---------------- block 0: finalize + reset ----------------
    if (u == 0) {
        if (tid == 0) {
            while (bar_sum(4) < NB) __nanosleep(64);
        }
        __syncthreads();
        double s = 0.0;
        if (tid < NB) s = (double)*(volatile float*)&g_Lp[tid];
        if (tid + 256 < NB) s += (double)*(volatile float*)&g_Lp[tid + 256];
#pragma unroll
        for (int o = 16; o; o >>= 1) s += __shfl_down_sync(0xffffffffu, s, o);
        if (lane == 0) s_dd[warp] = s;
        __syncthreads();
        if (tid == 0) {
            double t = 0.0;
#pragma unroll
            for (int i = 0; i < 8; i++) t += s_dd[i];
            out[0] = (float)(-t / (double)BATCH);
        }
        if (tid < 40) g_bars[tid >> 3][tid & 7] = 0;
        __threadfence();
    }
}

// ---------------- launcher ----------------
extern "C" void kernel_launch(void* const* d_in, const int* in_sizes, int n_in,
                              void* d_out, int out_size) {
    const float* feat_s     = (const float*)d_in[0];
    const float* feat_t     = (const float*)d_in[1];
    // d_in[2] = idx (unused; positives already in sample_idx[:,0])
    const int*   sample_idx = (const int*)d_in[3];
    const float* w_s        = (const float*)d_in[4];
    const float* b_s        = (const float*)d_in[5];
    const float* w_t        = (const float*)d_in[6];
    const float* b_t        = (const float*)d_in[7];
    const float* mem_v1     = (const float*)d_in[8];
    const float* mem_v2     = (const float*)d_in[9];
    float* out = (float*)d_out;

    cudaFuncSetAttribute(k_fused, cudaFuncAttributeMaxDynamicSharedMemorySize, SMEM_DYN);
    k_fused<<<NB, 256, SMEM_DYN>>>(feat_s, feat_t, sample_idx,
                                   w_s, b_s, w_t, b_t, mem_v1, mem_v2, out);
}

// round 10
// speedup vs baseline: 1.0963x; 1.0721x over previous
#include <cuda_runtime.h>
#include <cuda_bf16.h>
#include <cstdint>

// ---------------- problem constants ----------------
#define BATCH   64
#define FEAT    128
#define KDIM    2048
#define NDATA   100000
#define NSAMP   16385               // K+1
#define NPAIR   (BATCH * NSAMP)     // 1,048,640
#define NCE_T_INV (1.0f / 0.07f)
#define M_CONST (16384.0f / 100000.0f)
#define EPS_C   1e-7f

#define ESPLIT  32                  // embed k-splits per side (chunk 64)
#define KCH     64
#define RBLK    128                 // rows per logits tile
#define NTILE   ((NDATA + RBLK - 1) / RBLK)   // 782
#define SA      136                 // smem row stride (bf16 elems)

#define NPRE    128                 // k_pre blocks
#define NPB     296                 // k_post blocks per bank
#define NPOST   (2 * NPB)           // 592 = 148 SMs x occ 4
#define GSTRIDE (NPB * 256)         // 75776
#define GITER   14                  // ceil(NPAIR / GSTRIDE)

#define SMEM_PRE ((128 + 64) * SA * 2)   // 52224 B: Ws + Fs

// ---------------- device scratch (zero-init; reset each call) ----------------
__device__ float          g_partial[2][ESPLIT][FEAT * BATCH];   // [d*64+b]
__device__ uint32_t       g_hb[2][BATCH * FEAT / 2];
__device__ __nv_bfloat16  g_E[2][(size_t)NDATA * BATCH];
__device__ float          g_Zp[2][NPB];
__device__ float          g_Lp[NPOST];
__device__ int            g_bars[3][8];

// ---------------- helpers ----------------
__device__ __forceinline__ void ldsm_x4(uint32_t* r, uint32_t addr) {
    asm volatile("ldmatrix.sync.aligned.m8n8.x4.shared.b16 {%0,%1,%2,%3}, [%4];"
                 : "=r"(r[0]), "=r"(r[1]), "=r"(r[2]), "=r"(r[3]) : "r"(addr));
}
__device__ __forceinline__ void mma_bf16(float* c, const uint32_t* a, uint32_t b0, uint32_t b1) {
    asm volatile("mma.sync.aligned.m16n8k16.row.col.f32.bf16.bf16.f32 "
                 "{%0,%1,%2,%3}, {%4,%5,%6,%7}, {%8,%9}, {%0,%1,%2,%3};"
                 : "+f"(c[0]), "+f"(c[1]), "+f"(c[2]), "+f"(c[3])
                 : "r"(a[0]), "r"(a[1]), "r"(a[2]), "r"(a[3]), "r"(b0), "r"(b1));
}
__device__ __forceinline__ uint32_t pack_bf2(float x, float y) {
    __nv_bfloat162 h2 = __floats2bfloat162_rn(x, y);
    return *reinterpret_cast<uint32_t*>(&h2);
}
__device__ __forceinline__ int bar_sum(int idx) {
    volatile int* s = g_bars[idx];
    int t = 0;
#pragma unroll
    for (int i = 0; i < 8; i++) t += s[i];
    return t;
}
__device__ __forceinline__ void gbar(int idx, int u, int count) {
    __syncthreads();
    if (threadIdx.x == 0) {
        __threadfence();
        atomicAdd(&g_bars[idx][u & 7], 1);
        while (bar_sum(idx) < count) __nanosleep(64);
    }
    __syncthreads();
}

// ================= K_PRE: MMA embed split-K + l2norm (128 blocks) =================
__global__ __launch_bounds__(256) void k_pre(
    const float* __restrict__ fs, const float* __restrict__ ft,
    const float* __restrict__ ws, const float* __restrict__ bsv,
    const float* __restrict__ wt, const float* __restrict__ btv)
{
    extern __shared__ __align__(16) char dsm[];
    __shared__ float s_red[8];

    const int u    = blockIdx.x;
    const int tid  = threadIdx.x;
    const int lane = tid & 31, warp = tid >> 5;
    const int lr = lane & 7, q = lane >> 3;

    // ---- P0: embed GEMM via MMA, split-K (first 64 blocks) ----
    if (u < 2 * ESPLIT) {
        const int which = u >> 5;
        const int split = u & 31;
        const int k0 = split * KCH;
        const float* W = which ? wt : ws;
        const float* F = which ? ft : fs;

        uint16_t* Ws = reinterpret_cast<uint16_t*>(dsm);          // 128 x SA
        uint16_t* Fs = Ws + 128 * SA;                             // 64 x SA

#pragma unroll
        for (int j = 0; j < 8; j++) {
            const int i = tid + j * 256;
            const int row = i >> 4, c4 = i & 15;
            const float4 v = __ldg(reinterpret_cast<const float4*>(W + row * KDIM + k0) + c4);
            uint2 p;
            p.x = pack_bf2(v.x, v.y);
            p.y = pack_bf2(v.z, v.w);
            *reinterpret_cast<uint2*>(&Ws[row * SA + c4 * 4]) = p;
        }
#pragma unroll
        for (int j = 0; j < 4; j++) {
            const int i = tid + j * 256;
            const int row = i >> 4, c4 = i & 15;
            const float4 v = __ldg(reinterpret_cast<const float4*>(F + row * KDIM + k0) + c4);
            uint2 p;
            p.x = pack_bf2(v.x, v.y);
            p.y = pack_bf2(v.z, v.w);
            *reinterpret_cast<uint2*>(&Fs[row * SA + c4 * 4]) = p;
        }
        __syncthreads();

        const uint32_t a_base = (uint32_t)__cvta_generic_to_shared(Ws);
        const uint32_t b_base = (uint32_t)__cvta_generic_to_shared(Fs);
        const int mg = warp & 3, nh = warp >> 2;     // m128 = 4x32, n64 = 2x32
        const int a_r = lr + ((q & 1) << 3), a_k = (q >> 1) << 3;
        const int b_r = lr + ((q >> 1) << 3), b_k = (q & 1) << 3;

        float acc[2][4][4];
#pragma unroll
        for (int mh = 0; mh < 2; mh++)
#pragma unroll
            for (int nf = 0; nf < 4; nf++)
#pragma unroll
                for (int e = 0; e < 4; e++) acc[mh][nf][e] = 0.f;

#pragma unroll
        for (int ks = 0; ks < 4; ks++) {
            const int kk = ks * 16;
            uint32_t a0[4], a1[4], bb0[4], bb1[4];
            ldsm_x4(a0, a_base + (uint32_t)((mg * 32 + a_r) * SA + kk + a_k) * 2u);
            ldsm_x4(a1, a_base + (uint32_t)((mg * 32 + 16 + a_r) * SA + kk + a_k) * 2u);
            ldsm_x4(bb0, b_base + (uint32_t)((nh * 32 + b_r) * SA + kk + b_k) * 2u);
            ldsm_x4(bb1, b_base + (uint32_t)((nh * 32 + 16 + b_r) * SA + kk + b_k) * 2u);
            mma_bf16(acc[0][0], a0, bb0[0], bb0[1]);
            mma_bf16(acc[0][1], a0, bb0[2], bb0[3]);
            mma_bf16(acc[0][2], a0, bb1[0], bb1[1]);
            mma_bf16(acc[0][3], a0, bb1[2], bb1[3]);
            mma_bf16(acc[1][0], a1, bb0[0], bb0[1]);
            mma_bf16(acc[1][1], a1, bb0[2], bb0[3]);
            mma_bf16(acc[1][2], a1, bb1[0], bb1[1]);
            mma_bf16(acc[1][3], a1, bb1[2], bb1[3]);
        }

        float* outp = g_partial[which][split];
        const int er = lane >> 2, ec = lane & 3;
#pragma unroll
        for (int mh = 0; mh < 2; mh++)
#pragma unroll
            for (int nf = 0; nf < 4; nf++) {
                const int rd = mg * 32 + mh * 16 + er;
                const int cb = nh * 32 + nf * 8 + ec * 2;
                float2 v0 = make_float2(acc[mh][nf][0], acc[mh][nf][1]);
                float2 v1 = make_float2(acc[mh][nf][2], acc[mh][nf][3]);
                *reinterpret_cast<float2*>(&outp[rd * BATCH + cb]) = v0;
                *reinterpret_cast<float2*>(&outp[(rd + 8) * BATCH + cb]) = v1;
            }
    }
    gbar(0, u, NPRE);

    // ---- P1: reduce 32 splits + bias + l2norm + pack bf16 (all 128 blocks) ----
    {
        const int which = u >> 6;
        const int b     = u & 63;
        const float* bias = which ? btv : bsv;
        float s = 0.f;
        if (tid < 128) {
            const int d = tid;
#pragma unroll 8
            for (int sp = 0; sp < ESPLIT; sp++)
                s += __ldcg(&g_partial[which][sp][d * BATCH + b]);
            s += bias[d];
            float sq = s * s;
#pragma unroll
            for (int o = 16; o; o >>= 1) sq += __shfl_xor_sync(0xffffffffu, sq, o);
            if ((tid & 31) == 0) s_red[tid >> 5] = sq;
        }
        __syncthreads();
        if (tid < 128) {
            const float tot = s_red[0] + s_red[1] + s_red[2] + s_red[3];
            const float v = s * rsqrtf(tot);
            const float vn = __shfl_down_sync(0xffffffffu, v, 1);
            if ((tid & 1) == 0)
                g_hb[which][(b * FEAT + tid) >> 1] = pack_bf2(v, vn);
        }
    }
}

// ================= K_LOGITS: dense bf16 GEMM + fused exp (standalone, high occ) =================
// bank 0: v = hs vs mem_v2 ; bank 1: v = ht vs mem_v1
__global__ __launch_bounds__(256) void k_logits(const float* __restrict__ mem_v1,
                                                const float* __restrict__ mem_v2) {
    const int bank = blockIdx.y;
    const float* __restrict__ mem = bank ? mem_v1 : mem_v2;
    const int r_base = blockIdx.x * RBLK;

    __shared__ __nv_bfloat16 Vs[BATCH * SA];

    const int tid = threadIdx.x;
    for (int i = tid; i < BATCH * 64; i += 256) {
        const int row = i >> 6, c2 = i & 63;
        *reinterpret_cast<uint32_t*>(&Vs[row * SA + c2 * 2]) = __ldg(&g_hb[bank][i]);
    }
    __syncthreads();

    const uint32_t v_base = (uint32_t)__cvta_generic_to_shared(Vs);
    const int lane = tid & 31, warp = tid >> 5;
    const int lr = lane & 7, q = lane >> 3;

    const int row0 = r_base + warp * 16 + (lane >> 2);
    const int row1 = row0 + 8;
    const int rc0 = row0 < NDATA ? row0 : NDATA - 1;
    const int rc1 = row1 < NDATA ? row1 : NDATA - 1;
    const float* p0 = mem + (size_t)rc0 * FEAT + (lane & 3) * 2;
    const float* p1 = mem + (size_t)rc1 * FEAT + (lane & 3) * 2;

    const int b_row = lr + ((q >> 1) << 3);
    const int b_kh  = (q & 1) << 3;

    float acc[8][4];
#pragma unroll
    for (int f = 0; f < 8; f++)
#pragma unroll
        for (int e = 0; e < 4; e++) acc[f][e] = 0.f;

    float2 buf[2][4];
#define LOADK(s, ks) {                                                          \
        buf[s][0] = __ldcs(reinterpret_cast<const float2*>(p0 + (ks) * 16));      \
        buf[s][1] = __ldcs(reinterpret_cast<const float2*>(p1 + (ks) * 16));      \
        buf[s][2] = __ldcs(reinterpret_cast<const float2*>(p0 + (ks) * 16 + 8));  \
        buf[s][3] = __ldcs(reinterpret_cast<const float2*>(p1 + (ks) * 16 + 8)); }

    LOADK(0, 0);
    LOADK(1, 1);

#pragma unroll
    for (int ks = 0; ks < 8; ks++) {
        const int s = ks & 1;
        uint32_t a[4];
#pragma unroll
        for (int e = 0; e < 4; e++) a[e] = pack_bf2(buf[s][e].x, buf[s][e].y);
        if (ks < 6) LOADK(s, ks + 2);
        const int k0 = ks * 16;
#pragma unroll
        for (int nt = 0; nt < 4; nt++) {
            uint32_t bb[4];
            ldsm_x4(bb, v_base + (uint32_t)((nt * 16 + b_row) * SA + k0 + b_kh) * 2u);
            mma_bf16(acc[nt * 2 + 0], a, bb[0], bb[1]);
            mma_bf16(acc[nt * 2 + 1], a, bb[2], bb[3]);
        }
    }
#undef LOADK

    // epilogue: exp(logit/T) -> bf16 E[r][b]
    uint32_t* Eb = reinterpret_cast<uint32_t*>(g_E[bank]);
    const int cbase = (lane & 3) * 2;
#pragma unroll
    for (int f = 0; f < 8; f++) {
        const int c = (f >> 1) * 16 + (f & 1) * 8 + cbase;
        if (row0 < NDATA)
            Eb[(size_t)row0 * (BATCH / 2) + (c >> 1)] =
                pack_bf2(__expf(acc[f][0] * NCE_T_INV), __expf(acc[f][1] * NCE_T_INV));
        if (row1 < NDATA)
            Eb[(size_t)row1 * (BATCH / 2) + (c >> 1)] =
                pack_bf2(__expf(acc[f][2] * NCE_T_INV), __expf(acc[f][3] * NCE_T_INV));
    }
}

// ================= K_POST: gather + Z | sharded bar | loss + finalize (592 blocks) =================
__global__ __launch_bounds__(256, 4) void k_post(const int* __restrict__ samp,
                                                 float* __restrict__ out) {
    __shared__ float s_red[8];
    __shared__ float s_z;

    const int u    = blockIdx.x;
    const int tid  = threadIdx.x;
    const int lane = tid & 31, warp = tid >> 5;
    const int bank = (u >= NPB) ? 1 : 0;
    const int bx   = u - bank * NPB;
    const int pbase = bx * 256 + tid;

    // ---- gather into registers + per-block Z slot ----
    float gv[GITER];
#pragma unroll
    for (int i = 0; i < GITER; i++) {
        const int p = pbase + i * GSTRIDE;
        gv[i] = 0.f;
        if (p < NPAIR) {
            const int s = __ldg(&samp[p]);
            const int b = p / NSAMP;
            gv[i] = __bfloat162float(g_E[bank][(size_t)s * BATCH + b]);
        }
    }
    {
        float lsum = 0.f;
#pragma unroll
        for (int i = 0; i < GITER; i++) lsum += gv[i];
#pragma unroll
        for (int o = 16; o; o >>= 1) lsum += __shfl_xor_sync(0xffffffffu, lsum, o);
        if ((tid & 31) == 0) s_red[tid >> 5] = lsum;
        __syncthreads();
        if (tid == 0) {
            double tot = 0.0;
#pragma unroll
            for (int i = 0; i < 8; i++) tot += (double)s_red[i];
            g_Zp[bank][bx] = (float)tot;
        }
    }
    gbar(1, u, NPOST);

    // ---- each block reduces its bank's 296 Z slots (deterministic order) ----
    {
        float zv = *(volatile float*)&g_Zp[bank][tid < NPB ? tid : 0];
        if (tid >= NPB) zv = 0.f;
        if (tid + 256 < NPB) zv += *(volatile float*)&g_Zp[bank][tid + 256];
#pragma unroll
        for (int o = 16; o; o >>= 1) zv += __shfl_xor_sync(0xffffffffu, zv, o);
        if (lane == 0) s_red[warp] = zv;
        __syncthreads();
        if (tid == 0) {
            float zt = 0.f;
#pragma unroll
            for (int i = 0; i < 8; i++) zt += s_red[i];
            s_z = (float)((double)zt * ((double)NDATA / (double)NPAIR));
        }
        __syncthreads();
    }

    // ---- loss from registers (batched logs: 7 + 7) ----
    {
        const float zinv = 1.0f / s_z;
        float lsum = 0.f;
        float pn = 1.f, pd = 1.f;
#pragma unroll
        for (int i = 0; i < GITER; i++) {
            const int p = pbase + i * GSTRIDE;
            if (p < NPAIR) {
                const float x = gv[i] * zinv;
                const int b = p / NSAMP;
                const bool pos = (p - b * NSAMP) == 0;
                pn *= pos ? x : M_CONST;
                pd *= x + M_CONST + EPS_C;
            }
            if (i == 6 || i == GITER - 1) {
                lsum += __logf(pn / pd);
                pn = 1.f; pd = 1.f;
            }
        }
#pragma unroll
        for (int o = 16; o; o >>= 1) lsum += __shfl_xor_sync(0xffffffffu, lsum, o);
        __syncthreads();
        if ((tid & 31) == 0) s_red[tid >> 5] = lsum;
        __syncthreads();
        if (tid == 0) {
            double tot = 0.0;
#pragma unroll
            for (int i = 0; i < 8; i++) tot += (double)s_red[i];
            g_Lp[u] = (float)tot;
            __threadfence();
            atomicAdd(&g_bars[2][u & 7], 1);
        }
    }

    // ---- block 0: finalize + reset ----
    if (u == 0) {
        if (tid == 0) {
            while (bar_sum(2) < NPOST) __nanosleep(64);
        }
        __syncthreads();
        double s = (double)*(volatile float*)&g_Lp[tid];
        s += (double)*(volatile float*)&g_Lp[tid + 256];
        if (tid + 512 < NPOST) s += (double)*(volatile float*)&g_Lp[tid + 512];
#pragma unroll
        for (int o = 16; o; o >>= 1) s += __shfl_down_sync(0xffffffffu, s, o);
        __shared__ double s_dd[8];
        if (lane == 0) s_dd[warp] = s;
        __syncthreads();
        if (tid == 0) {
            double t = 0.0;
#pragma unroll
            for (int i = 0; i < 8; i++) t += s_dd[i];
            out[0] = (float)(-t / (double)BATCH);
        }
        // reset all barrier shards for the next graph replay
        if (tid < 24) g_bars[tid >> 3][tid & 7] = 0;
        __threadfence();
    }
}

// ---------------- launcher: 3 kernels ----------------
extern "C" void kernel_launch(void* const* d_in, const int* in_sizes, int n_in,
                              void* d_out, int out_size) {
    const float* feat_s     = (const float*)d_in[0];
    const float* feat_t     = (const float*)d_in[1];
    // d_in[2] = idx (unused; positives already in sample_idx[:,0])
    const int*   sample_idx = (const int*)d_in[3];
    const float* w_s        = (const float*)d_in[4];
    const float* b_s        = (const float*)d_in[5];
    const float* w_t        = (const float*)d_in[6];
    const float* b_t        = (const float*)d_in[7];
    const float* mem_v1     = (const float*)d_in[8];
    const float* mem_v2     = (const float*)d_in[9];
    float* out = (float*)d_out;

    cudaFuncSetAttribute(k_pre, cudaFuncAttributeMaxDynamicSharedMemorySize, SMEM_PRE);
    k_pre<<<NPRE, 256, SMEM_PRE>>>(feat_s, feat_t, w_s, b_s, w_t, b_t);
    k_logits<<<dim3(NTILE, 2), 256>>>(mem_v1, mem_v2);
    k_post<<<NPOST, 256>>>(sample_idx, out);
}

// round 11
// speedup vs baseline: 1.2930x; 1.1793x over previous
#include <cuda_runtime.h>
#include <cuda_bf16.h>
#include <cstdint>

// ---------------- problem constants ----------------
#define BATCH   64
#define FEAT    128
#define KDIM    2048
#define NDATA   100000
#define NSAMP   16385               // K+1
#define NPAIR   (BATCH * NSAMP)     // 1,048,640
#define NCE_T_INV (1.0f / 0.07f)
#define M_CONST (16384.0f / 100000.0f)
#define EPS_C   1e-7f

#define ESPLIT  32                  // embed k-splits per side (chunk 64)
#define KCH     64
#define RBLK    128                 // rows per logits tile
#define NTILE   ((NDATA + RBLK - 1) / RBLK)   // 782
#define SA      136                 // smem row stride (bf16 elems)

#define NBB     148                 // blocks per bank
#define NB      (2 * NBB)           // 296 blocks = 148 SMs x occ 2
#define GSTRIDE (NBB * 256)         // 37888
#define GITER   28                  // ceil(NPAIR / GSTRIDE)

#define SMEM_DYN ((128 + 64) * SA * 2)   // 52224 B: Ws+Fs (P0) / Vs (P2)

// ---------------- device scratch (zero-init; reset each call) ----------------
__device__ float          g_partial[2][ESPLIT][FEAT * BATCH];   // [d*64+b]
__device__ float          g_hs[2][FEAT * BATCH];                // pre-norm h, [d*64+b]
__device__ float          g_nrm[2][BATCH];                      // sum of squares per b
__device__ __nv_bfloat16  g_E[2][(size_t)NDATA * BATCH];
__device__ float          g_Zp[2][NBB];
__device__ float          g_Lp[NB];
__device__ int            g_bars[5][8];

// ---------------- helpers ----------------
__device__ __forceinline__ void ldsm_x4(uint32_t* r, uint32_t addr) {
    asm volatile("ldmatrix.sync.aligned.m8n8.x4.shared.b16 {%0,%1,%2,%3}, [%4];"
                 : "=r"(r[0]), "=r"(r[1]), "=r"(r[2]), "=r"(r[3]) : "r"(addr));
}
__device__ __forceinline__ void mma_bf16(float* c, const uint32_t* a, uint32_t b0, uint32_t b1) {
    asm volatile("mma.sync.aligned.m16n8k16.row.col.f32.bf16.bf16.f32 "
                 "{%0,%1,%2,%3}, {%4,%5,%6,%7}, {%8,%9}, {%0,%1,%2,%3};"
                 : "+f"(c[0]), "+f"(c[1]), "+f"(c[2]), "+f"(c[3])
                 : "r"(a[0]), "r"(a[1]), "r"(a[2]), "r"(a[3]), "r"(b0), "r"(b1));
}
__device__ __forceinline__ uint32_t pack_bf2(float x, float y) {
    __nv_bfloat162 h2 = __floats2bfloat162_rn(x, y);
    return *reinterpret_cast<uint32_t*>(&h2);
}
__device__ __forceinline__ float ld_e_cg(const __nv_bfloat16* p) {
    unsigned short v;
    asm volatile("ld.global.cg.u16 %0, [%1];" : "=h"(v) : "l"(p));
    __nv_bfloat16 b;
    *reinterpret_cast<unsigned short*>(&b) = v;
    return __bfloat162float(b);
}
__device__ __forceinline__ int bar_sum(int idx) {
    volatile int* s = g_bars[idx];
    int t = 0;
#pragma unroll
    for (int i = 0; i < 8; i++) t += s[i];
    return t;
}
__device__ __forceinline__ void gbar(int idx, int u) {
    __syncthreads();
    if (threadIdx.x == 0) {
        __threadfence();
        atomicAdd(&g_bars[idx][u & 7], 1);
        while (bar_sum(idx) < NB) __nanosleep(64);
    }
    __syncthreads();
}

// ================= the one kernel (occ 2) =================
__global__ __launch_bounds__(256, 2) void k_fused(
    const float* __restrict__ fs, const float* __restrict__ ft,
    const int*   __restrict__ samp,
    const float* __restrict__ ws, const float* __restrict__ bsv,
    const float* __restrict__ wt, const float* __restrict__ btv,
    const float* __restrict__ mem_v1, const float* __restrict__ mem_v2,
    float* __restrict__ out)
{
    extern __shared__ __align__(16) char dsm[];
    __shared__ float  s_red[8];
    __shared__ double s_dd[8];
    __shared__ float  s_z;
    __shared__ float  s_rinv[64];

    const int u    = blockIdx.x;
    const int tid  = threadIdx.x;
    const int lane = tid & 31, warp = tid >> 5;
    const int lr = lane & 7, q = lane >> 3;

    // ---------------- P0: embed GEMM via MMA, split-K (64 blocks) ----------------
    if (u < 2 * ESPLIT) {
        const int which = u >> 5;
        const int split = u & 31;
        const int k0 = split * KCH;
        const float* W = which ? wt : ws;
        const float* F = which ? ft : fs;

        uint16_t* Ws = reinterpret_cast<uint16_t*>(dsm);          // 128 x SA
        uint16_t* Fs = Ws + 128 * SA;                             // 64 x SA

#pragma unroll
        for (int j = 0; j < 8; j++) {
            const int i = tid + j * 256;
            const int row = i >> 4, c4 = i & 15;
            const float4 v = __ldg(reinterpret_cast<const float4*>(W + row * KDIM + k0) + c4);
            uint2 p;
            p.x = pack_bf2(v.x, v.y);
            p.y = pack_bf2(v.z, v.w);
            *reinterpret_cast<uint2*>(&Ws[row * SA + c4 * 4]) = p;
        }
#pragma unroll
        for (int j = 0; j < 4; j++) {
            const int i = tid + j * 256;
            const int row = i >> 4, c4 = i & 15;
            const float4 v = __ldg(reinterpret_cast<const float4*>(F + row * KDIM + k0) + c4);
            uint2 p;
            p.x = pack_bf2(v.x, v.y);
            p.y = pack_bf2(v.z, v.w);
            *reinterpret_cast<uint2*>(&Fs[row * SA + c4 * 4]) = p;
        }
        __syncthreads();

        const uint32_t a_base = (uint32_t)__cvta_generic_to_shared(Ws);
        const uint32_t b_base = (uint32_t)__cvta_generic_to_shared(Fs);
        const int mg = warp & 3, nh = warp >> 2;
        const int a_r = lr + ((q & 1) << 3), a_k = (q >> 1) << 3;
        const int b_r = lr + ((q >> 1) << 3), b_k = (q & 1) << 3;

        float acc[2][4][4];
#pragma unroll
        for (int mh = 0; mh < 2; mh++)
#pragma unroll
            for (int nf = 0; nf < 4; nf++)
#pragma unroll
                for (int e = 0; e < 4; e++) acc[mh][nf][e] = 0.f;

#pragma unroll
        for (int ks = 0; ks < 4; ks++) {
            const int kk = ks * 16;
            uint32_t a0[4], a1[4], bb0[4], bb1[4];
            ldsm_x4(a0, a_base + (uint32_t)((mg * 32 + a_r) * SA + kk + a_k) * 2u);
            ldsm_x4(a1, a_base + (uint32_t)((mg * 32 + 16 + a_r) * SA + kk + a_k) * 2u);
            ldsm_x4(bb0, b_base + (uint32_t)((nh * 32 + b_r) * SA + kk + b_k) * 2u);
            ldsm_x4(bb1, b_base + (uint32_t)((nh * 32 + 16 + b_r) * SA + kk + b_k) * 2u);
            mma_bf16(acc[0][0], a0, bb0[0], bb0[1]);
            mma_bf16(acc[0][1], a0, bb0[2], bb0[3]);
            mma_bf16(acc[0][2], a0, bb1[0], bb1[1]);
            mma_bf16(acc[0][3], a0, bb1[2], bb1[3]);
            mma_bf16(acc[1][0], a1, bb0[0], bb0[1]);
            mma_bf16(acc[1][1], a1, bb0[2], bb0[3]);
            mma_bf16(acc[1][2], a1, bb1[0], bb1[1]);
            mma_bf16(acc[1][3], a1, bb1[2], bb1[3]);
        }

        float* outp = g_partial[which][split];
        const int er = lane >> 2, ec = lane & 3;
#pragma unroll
        for (int mh = 0; mh < 2; mh++)
#pragma unroll
            for (int nf = 0; nf < 4; nf++) {
                const int rd = mg * 32 + mh * 16 + er;
                const int cb = nh * 32 + nf * 8 + ec * 2;
                float2 v0 = make_float2(acc[mh][nf][0], acc[mh][nf][1]);
                float2 v1 = make_float2(acc[mh][nf][2], acc[mh][nf][3]);
                *reinterpret_cast<float2*>(&outp[rd * BATCH + cb]) = v0;
                *reinterpret_cast<float2*>(&outp[(rd + 8) * BATCH + cb]) = v1;
            }
    }
    gbar(0, u);

    // ---------------- P1a: COALESCED split-reduce + bias + sq-norm via REDG (64 blocks) ----------------
    if (u < 64) {
        const int which = u >> 5;
        const int i = (u & 31) * 256 + tid;       // linear -> coalesced
        const int d = i >> 6, b = i & 63;
        const float* bias = which ? btv : bsv;
        float s = 0.f;
#pragma unroll
        for (int sp = 0; sp < ESPLIT; sp++)
            s += __ldcg(&g_partial[which][sp][i]);
        s += __ldg(&bias[d]);
        g_hs[which][i] = s;
        atomicAdd(&g_nrm[which][b], s * s);       // 32 distinct b per warp -> spread REDG
    }
    gbar(1, u);

    // ---------------- P2: dense logits GEMM + fused exp (front-batched) ----------------
    const int bank = (u >= NBB) ? 1 : 0;
    const int bx = u - bank * NBB;
    {
        const float* __restrict__ mem = bank ? mem_v1 : mem_v2;
        uint16_t* Vs = reinterpret_cast<uint16_t*>(dsm);          // 64 x SA

        // build Vs from g_hs + g_nrm (normalize + bf16 + transpose)
        if (tid < 64) s_rinv[tid] = rsqrtf(__ldcg(&g_nrm[bank][tid]));
        __syncthreads();
        {
            const float* hsrc = g_hs[bank];
#pragma unroll 8
            for (int it = 0; it < 32; it++) {
                const int i = it * 256 + tid;
                const int d = i >> 6, b = i & 63;
                const float v = __ldcg(&hsrc[i]) * s_rinv[b];
                const __nv_bfloat16 hv = __float2bfloat16(v);
                Vs[b * SA + d] = *reinterpret_cast<const uint16_t*>(&hv);
            }
        }
        __syncthreads();

        const uint32_t v_base = (uint32_t)__cvta_generic_to_shared(Vs);
        const int b_row = lr + ((q >> 1) << 3);
        const int b_kh  = (q & 1) << 3;
        uint32_t* Eb = reinterpret_cast<uint32_t*>(g_E[bank]);

        for (int tile = bx; tile < NTILE; tile += NBB) {
            const int r_base = tile * RBLK;
            const int row0 = r_base + warp * 16 + (lane >> 2);
            const int row1 = row0 + 8;
            const int rc0 = row0 < NDATA ? row0 : NDATA - 1;
            const int rc1 = row1 < NDATA ? row1 : NDATA - 1;
            const float* p0 = mem + (size_t)rc0 * FEAT + (lane & 3) * 2;
            const float* p1 = mem + (size_t)rc1 * FEAT + (lane & 3) * 2;

            // front-batch: 32 independent LDG.64 per thread
            float2 rbuf[32];
#pragma unroll
            for (int ks = 0; ks < 8; ks++) {
                rbuf[ks * 4 + 0] = __ldcs(reinterpret_cast<const float2*>(p0 + ks * 16));
                rbuf[ks * 4 + 1] = __ldcs(reinterpret_cast<const float2*>(p1 + ks * 16));
                rbuf[ks * 4 + 2] = __ldcs(reinterpret_cast<const float2*>(p0 + ks * 16 + 8));
                rbuf[ks * 4 + 3] = __ldcs(reinterpret_cast<const float2*>(p1 + ks * 16 + 8));
            }

            float acc[8][4];
#pragma unroll
            for (int f = 0; f < 8; f++)
#pragma unroll
                for (int e = 0; e < 4; e++) acc[f][e] = 0.f;

#pragma unroll
            for (int ks = 0; ks < 8; ks++) {
                uint32_t a[4];
#pragma unroll
                for (int e = 0; e < 4; e++)
                    a[e] = pack_bf2(rbuf[ks * 4 + e].x, rbuf[ks * 4 + e].y);
                const int k0 = ks * 16;
#pragma unroll
                for (int nt = 0; nt < 4; nt++) {
                    uint32_t bb[4];
                    ldsm_x4(bb, v_base + (uint32_t)((nt * 16 + b_row) * SA + k0 + b_kh) * 2u);
                    mma_bf16(acc[nt * 2 + 0], a, bb[0], bb[1]);
                    mma_bf16(acc[nt * 2 + 1], a, bb[2], bb[3]);
                }
            }

            const int cbase = (lane & 3) * 2;
#pragma unroll
            for (int f = 0; f < 8; f++) {
                const int c = (f >> 1) * 16 + (f & 1) * 8 + cbase;
                if (row0 < NDATA)
                    Eb[(size_t)row0 * (BATCH / 2) + (c >> 1)] =
                        pack_bf2(__expf(acc[f][0] * NCE_T_INV), __expf(acc[f][1] * NCE_T_INV));
                if (row1 < NDATA)
                    Eb[(size_t)row1 * (BATCH / 2) + (c >> 1)] =
                        pack_bf2(__expf(acc[f][2] * NCE_T_INV), __expf(acc[f][3] * NCE_T_INV));
            }
        }
    }
    gbar(2, u);

    // ---------------- P3: gather into registers + per-block Z slot ----------------
    const int pbase = bx * 256 + tid;
    float gv[GITER];
    {
#pragma unroll
        for (int i = 0; i < GITER; i++) {
            const int p = pbase + i * GSTRIDE;
            gv[i] = 0.f;
            if (p < NPAIR) {
                const int s = __ldg(&samp[p]);
                const int b = p / NSAMP;
                gv[i] = ld_e_cg(&g_E[bank][(size_t)s * BATCH + b]);
            }
        }
        float lsum = 0.f;
#pragma unroll
        for (int i = 0; i < GITER; i++) lsum += gv[i];
#pragma unroll
        for (int o = 16; o; o >>= 1) lsum += __shfl_xor_sync(0xffffffffu, lsum, o);
        if ((tid & 31) == 0) s_red[tid >> 5] = lsum;
        __syncthreads();
        if (tid == 0) {
            double tot = 0.0;
#pragma unroll
            for (int i = 0; i < 8; i++) tot += (double)s_red[i];
            g_Zp[bank][bx] = (float)tot;
        }
    }
    gbar(3, u);

    // each block reduces its bank's Z slots
    {
        float zv = (tid < NBB) ? *(volatile float*)&g_Zp[bank][tid] : 0.f;
#pragma unroll
        for (int o = 16; o; o >>= 1) zv += __shfl_xor_sync(0xffffffffu, zv, o);
        if (lane == 0) s_red[warp] = zv;
        __syncthreads();
        if (tid == 0) {
            float zt = 0.f;
#pragma unroll
            for (int i = 0; i < 8; i++) zt += s_red[i];
            s_z = (float)((double)zt * ((double)NDATA / (double)NPAIR));
        }
        __syncthreads();
    }

    // ---------------- P4: loss from registers (batched logs) ----------------
    {
        const float zinv = 1.0f / s_z;
        float lsum = 0.f;
        float pn = 1.f, pd = 1.f;
#pragma unroll
        for (int i = 0; i < GITER; i++) {
            const int p = pbase + i * GSTRIDE;
            if (p < NPAIR) {
                const float x = gv[i] * zinv;
                const int b = p / NSAMP;
                const bool pos = (p - b * NSAMP) == 0;
                pn *= pos ? x : M_CONST;
                pd *= x + M_CONST + EPS_C;
            }
            if (i == 13 || i == GITER - 1) {
                lsum += __logf(pn / pd);
                pn = 1.f; pd = 1.f;
            }
        }
#pragma unroll
        for (int o = 16; o; o >>= 1) lsum += __shfl_xor_sync(0xffffffffu, lsum, o);
        __syncthreads();
        if ((tid & 31) == 0) s_red[tid >> 5] = lsum;
        __syncthreads();
        if (tid == 0) {
            double tot = 0.0;
#pragma unroll
            for (int i = 0; i < 8; i++) tot += (double)s_red[i];
            g_Lp[u] = (float)tot;
            __threadfence();
            atomicAdd(&g_bars[4][u & 7], 1);
        }
    }

    // ---------------- block 0: finalize + reset ----------------
    if (u == 0) {
        if (tid == 0) {
            while (bar_sum(4) < NB) __nanosleep(64);
        }
        __syncthreads();
        double s = 0.0;
        if (tid < NB) s = (double)*(volatile float*)&g_Lp[tid];
        if (tid + 256 < NB) s += (double)*(volatile float*)&g_Lp[tid + 256];
#pragma unroll
        for (int o = 16; o; o >>= 1) s += __shfl_down_sync(0xffffffffu, s, o);
        if (lane == 0) s_dd[warp] = s;
        __syncthreads();
        if (tid == 0) {
            double t = 0.0;
#pragma unroll
            for (int i = 0; i < 8; i++) t += s_dd[i];
            out[0] = (float)(-t / (double)BATCH);
        }
        // reset barrier shards + norm accumulators for the next graph replay
        if (tid < 40) g_bars[tid >> 3][tid & 7] = 0;
        if (tid < 128) g_nrm[tid >> 6][tid & 63] = 0.f;
        __threadfence();
    }
}

// ---------------- launcher ----------------
extern "C" void kernel_launch(void* const* d_in, const int* in_sizes, int n_in,
                              void* d_out, int out_size) {
    const float* feat_s     = (const float*)d_in[0];
    const float* feat_t     = (const float*)d_in[1];
    // d_in[2] = idx (unused; positives already in sample_idx[:,0])
    const int*   sample_idx = (const int*)d_in[3];
    const float* w_s        = (const float*)d_in[4];
    const float* b_s        = (const float*)d_in[5];
    const float* w_t        = (const float*)d_in[6];
    const float* b_t        = (const float*)d_in[7];
    const float* mem_v1     = (const float*)d_in[8];
    const float* mem_v2     = (const float*)d_in[9];
    float* out = (float*)d_out;

    cudaFuncSetAttribute(k_fused, cudaFuncAttributeMaxDynamicSharedMemorySize, SMEM_DYN);
    k_fused<<<NB, 256, SMEM_DYN>>>(feat_s, feat_t, sample_idx,
                                   w_s, b_s, w_t, b_t, mem_v1, mem_v2, out);
}